// round 12
// baseline (speedup 1.0000x reference)
#include <cuda_runtime.h>

#define NN 50000
#define NE 800000
#define D  128
#define DE 64
#define CAP 80

typedef unsigned long long ull;

// ---------------- device scratch (no allocs allowed) ----------------
__device__ __align__(16) int   g_deg [NN];
__device__ __align__(16) float g_norm[NN];
__device__ __align__(16) float g_h   [NN * D];     // nfeat@Wn + bn
__device__ __align__(16) float g_g   [NN * D];     // norm[n] * h[n]
__device__ __align__(16) float g_agge[NN * DE];    // sum_{e->n} norm[src]*efeat
__device__ __align__(16) float g_se  [NN];         // sum_{e->n} norm[src]
__device__ __align__(16) int   g_perm[NN * CAP];   // per-dst src list
__device__ __align__(16) int2  g_ovf [2048];       // overflow {src, dst}
__device__ int g_novf;

// ---------------- PTX helpers ----------------
__device__ __forceinline__ void fma2(ull &d, ull a, ull b) {
    asm("fma.rn.f32x2 %0, %1, %2, %0;" : "+l"(d) : "l"(a), "l"(b));
}
__device__ __forceinline__ void add2(ull &d, ull a) {
    asm("add.rn.f32x2 %0, %0, %1;" : "+l"(d) : "l"(a));
}
__device__ __forceinline__ ull dup2(float x) {
    ull r; asm("mov.b64 %0, {%1, %1};" : "=l"(r) : "f"(x)); return r;
}
__device__ __forceinline__ ull pack2(float a, float b) {
    ull r; asm("mov.b64 %0, {%1, %2};" : "=l"(r) : "f"(a), "f"(b)); return r;
}
__device__ __forceinline__ float2 unpk(ull v) {
    float2 r; asm("mov.b64 {%0, %1}, %2;" : "=f"(r.x), "=f"(r.y) : "l"(v)); return r;
}
__device__ __forceinline__ void red4(float* p, float4 v) {
    asm volatile("red.global.add.v4.f32 [%0], {%1, %2, %3, %4};"
                 :: "l"(p), "f"(v.x), "f"(v.y), "f"(v.z), "f"(v.w) : "memory");
}
__device__ __forceinline__ ulonglong2 ldg2(const ull* p) {
    ulonglong2 r;
    asm("ld.global.nc.v2.u64 {%0, %1}, [%2];" : "=l"(r.x), "=l"(r.y) : "l"(p));
    return r;
}
// streaming 16B load with evict-first policy
__device__ __forceinline__ float4 ldg4_ef(const float* p, ull pol) {
    float4 r;
    asm("ld.global.nc.L2::cache_hint.v4.f32 {%0, %1, %2, %3}, [%4], %5;"
        : "=f"(r.x), "=f"(r.y), "=f"(r.z), "=f"(r.w) : "l"(p), "l"(pol));
    return r;
}
__device__ __forceinline__ float ldgf(const float* p) {
    float r; asm("ld.global.nc.f32 %0, [%1];" : "=f"(r) : "l"(p)); return r;
}

// ---------------- K0: zero scratch ----------------
__global__ void k_zero() {
    int i = blockIdx.x * blockDim.x + threadIdx.x;
    int st = gridDim.x * blockDim.x;
    float4 z = make_float4(0.f, 0.f, 0.f, 0.f);
    for (int j = i; j < NN * DE / 4; j += st) ((float4*)g_agge)[j] = z;
    for (int j = i; j < NN; j += st) { g_se[j] = 0.f; g_deg[j] = 0; }
    if (i == 0) g_novf = 0;
}

// ---------------- K1: build per-dst src buckets + degree ----------------
__global__ void k_build(const int* __restrict__ src, const int* __restrict__ dst) {
    int e = blockIdx.x * blockDim.x + threadIdx.x;
    if (e >= NE) return;
    int d = dst[e], s = src[e];
    int c = atomicAdd(&g_deg[d], 1);
    if (c < CAP) {
        g_perm[d * CAP + c] = s;
    } else {
        int o = atomicAdd(&g_novf, 1);
        if (o < 2048) g_ovf[o] = make_int2(s, d);
    }
}

// ---------------- K1b: norm = (deg+1)^-1/2 ----------------
__global__ void k_norm() {
    int i = blockIdx.x * blockDim.x + threadIdx.x;
    if (i < NN) g_norm[i] = rsqrtf((float)g_deg[i] + 1.0f);
}

// ---------------- KA: edge-parallel efeat scatter (2 edges per round) ----------------
__global__ __launch_bounds__(256) void k_edge_e(
    const int* __restrict__ src, const int* __restrict__ dst,
    const float* __restrict__ efeat)
{
    int lane = threadIdx.x & 31;
    int warp = (blockIdx.x * blockDim.x + threadIdx.x) >> 5;   // 25000 warps
    int e0   = warp * 32;
    if (e0 >= NE) return;

    int s = src[e0 + lane];
    int d = dst[e0 + lane];
    float ns = ldgf(&g_norm[s]);
    atomicAdd(&g_se[d], ns);

    ull pol;
    asm("createpolicy.fractional.L2::evict_first.b64 %0, 1.0;" : "=l"(pol));

    int half = lane >> 4;        // 0 or 1: which edge of the pair
    int l16  = lane & 15;
    const float* ep = &efeat[(size_t)e0 * DE + 4 * l16];

    #pragma unroll
    for (int j = 0; j < 32; j += 2) {
        int idx = j + half;
        int   dj  = __shfl_sync(0xffffffffu, d, idx);
        float nsj = __shfl_sync(0xffffffffu, ns, idx);
        float4 ev = ldg4_ef(ep + (size_t)idx * DE, pol);
        red4(&g_agge[(size_t)dj * DE + 4 * l16],
             make_float4(nsj * ev.x, nsj * ev.y, nsj * ev.z, nsj * ev.w));
    }
}

// ---------------- K2: pure node GEMM  h = nfeat@Wn + bn  (no dependencies!) -------
__global__ __launch_bounds__(256) void k_gemmN(
    const float* __restrict__ nfeat, const float* __restrict__ Wn,
    const float* __restrict__ bn)
{
    extern __shared__ ull smn[];
    ull*   sW  = smn;                       // [128][64] u64 (Wn dim-pairs) = 64 KB
    float* sNf = (float*)(smn + 128 * 64);  // [k][node] = 32 KB

    int t = threadIdx.x, lane = t & 31, w = t >> 5;

    const ulonglong2* Wn128 = (const ulonglong2*)Wn;
    ulonglong2* sW2 = (ulonglong2*)sW;
    for (int i = t; i < 128 * 64 / 2; i += 256) sW2[i] = Wn128[i];

    float4 bnv = *(const float4*)&bn[4 * lane];
    ull b01 = pack2(bnv.x, bnv.y), b23 = pack2(bnv.z, bnv.w);

    int nodeL = t & 63;   // load-phase node
    int q     = t >> 6;   // load-phase dim quarter

    const int NT = (NN + 63) / 64;
    for (int tile = blockIdx.x; tile < NT; tile += gridDim.x) {
        __syncthreads();
        int gn = tile * 64 + nodeL;
        #pragma unroll
        for (int i = 0; i < 8; i++) {
            int k0 = 32 * q + 4 * i;
            float4 v = make_float4(0.f, 0.f, 0.f, 0.f);
            if (gn < NN) v = *(const float4*)&nfeat[(size_t)gn * D + k0];
            sNf[(k0 + 0) * 64 + nodeL] = v.x;
            sNf[(k0 + 1) * 64 + nodeL] = v.y;
            sNf[(k0 + 2) * 64 + nodeL] = v.z;
            sNf[(k0 + 3) * 64 + nodeL] = v.w;
        }
        __syncthreads();

        ull acc[8][2];
        #pragma unroll
        for (int j = 0; j < 8; j++) { acc[j][0] = b01; acc[j][1] = b23; }

        #pragma unroll 8
        for (int k = 0; k < 128; k++) {
            ulonglong2 wv = *(const ulonglong2*)&sW[k * 64 + 2 * lane];
            float4 f0 = *(const float4*)&sNf[k * 64 + 8 * w];
            float4 f1 = *(const float4*)&sNf[k * 64 + 8 * w + 4];
            float fv[8] = {f0.x, f0.y, f0.z, f0.w, f1.x, f1.y, f1.z, f1.w};
            #pragma unroll
            for (int j = 0; j < 8; j++) {
                ull dj = dup2(fv[j]);
                fma2(acc[j][0], dj, wv.x);
                fma2(acc[j][1], dj, wv.y);
            }
        }

        #pragma unroll
        for (int j = 0; j < 8; j++) {
            int n = tile * 64 + 8 * w + j;
            if (n >= NN) continue;
            float2 p0 = unpk(acc[j][0]), p1 = unpk(acc[j][1]);
            *(float4*)&g_h[(size_t)n * D + 4 * lane] =
                make_float4(p0.x, p0.y, p1.x, p1.y);
        }
    }
}

// ---------------- K2b: scale pass  g_g = norm*h ; out = (h+resid)/deg ----------------
__global__ __launch_bounds__(256) void k_scale(
    const float* __restrict__ resid, float* __restrict__ out)
{
    int i = blockIdx.x * blockDim.x + threadIdx.x;   // one float4 per thread
    if (i >= NN * (D / 4)) return;
    int n  = i >> 5;
    int c4 = (i & 31) * 4;

    float dv  = (float)g_deg[n] + 1.0f;
    float inv = 1.0f / dv;
    float nr  = g_norm[n];
    float4 h4 = *(const float4*)&g_h[(size_t)n * D + c4];
    float4 r4 = *(const float4*)&resid[c4];
    *(float4*)&g_g[(size_t)n * D + c4] =
        make_float4(nr * h4.x, nr * h4.y, nr * h4.z, nr * h4.w);
    *(float4*)&out[(size_t)n * D + c4] =
        make_float4((h4.x + r4.x) * inv, (h4.y + r4.y) * inv,
                    (h4.z + r4.z) * inv, (h4.w + r4.w) * inv);
}

// ---------------- K3: tiled GEMM  out += norm * (agge@We + se*be)  [red4] ----------
__global__ __launch_bounds__(256) void k_gemm2(
    const float* __restrict__ We, const float* __restrict__ be,
    float* __restrict__ out)
{
    extern __shared__ ull smg[];
    ull*   sWe = smg;                      // [64][64] u64 (We dim-pairs) = 32 KB
    float* sAg = (float*)(smg + 64 * 64);  // [k][node] = 16 KB

    int t = threadIdx.x, lane = t & 31, w = t >> 5;

    const ulonglong2* We128 = (const ulonglong2*)We;
    ulonglong2* sWe2 = (ulonglong2*)sWe;
    for (int i = t; i < 64 * 64 / 2; i += 256) sWe2[i] = We128[i];

    float4 be4 = *(const float4*)&be[4 * lane];

    int nodeL = t & 63;
    int q     = t >> 6;   // 4 quarters x 16 k each

    const int NT = (NN + 63) / 64;
    for (int tile = blockIdx.x; tile < NT; tile += gridDim.x) {
        __syncthreads();
        int gn = tile * 64 + nodeL;
        #pragma unroll
        for (int i = 0; i < 4; i++) {
            int k0 = 16 * q + 4 * i;
            float4 v = make_float4(0.f, 0.f, 0.f, 0.f);
            if (gn < NN) v = *(const float4*)&g_agge[(size_t)gn * DE + k0];
            sAg[(k0 + 0) * 64 + nodeL] = v.x;
            sAg[(k0 + 1) * 64 + nodeL] = v.y;
            sAg[(k0 + 2) * 64 + nodeL] = v.z;
            sAg[(k0 + 3) * 64 + nodeL] = v.w;
        }
        __syncthreads();

        ull acc[8][2];
        #pragma unroll
        for (int j = 0; j < 8; j++) { acc[j][0] = 0ULL; acc[j][1] = 0ULL; }

        #pragma unroll 8
        for (int k = 0; k < 64; k++) {
            ulonglong2 wv = *(const ulonglong2*)&sWe[k * 64 + 2 * lane];
            float4 f0 = *(const float4*)&sAg[k * 64 + 8 * w];
            float4 f1 = *(const float4*)&sAg[k * 64 + 8 * w + 4];
            float fv[8] = {f0.x, f0.y, f0.z, f0.w, f1.x, f1.y, f1.z, f1.w};
            #pragma unroll
            for (int j = 0; j < 8; j++) {
                ull dj = dup2(fv[j]);
                fma2(acc[j][0], dj, wv.x);
                fma2(acc[j][1], dj, wv.y);
            }
        }

        #pragma unroll
        for (int j = 0; j < 8; j++) {
            int n = tile * 64 + 8 * w + j;
            if (n >= NN) continue;
            float nr = g_norm[n];
            float se = g_se[n];
            float2 p0 = unpk(acc[j][0]), p1 = unpk(acc[j][1]);
            red4(&out[(size_t)n * D + 4 * lane],
                 make_float4(nr * (p0.x + se * be4.x), nr * (p0.y + se * be4.y),
                             nr * (p1.x + se * be4.z), nr * (p1.y + se * be4.w)));
        }
    }
}

// ---------------- K4: node-parallel g_g gather (no smem; red4 epilogue) ----------------
__global__ __launch_bounds__(256) void k_gath(float* __restrict__ out)
{
    int t = threadIdx.x, lane = t & 31, w = t >> 5;
    int n = blockIdx.x * 8 + w;   // grid = 6250 * 8 warps = 50000
    if (n >= NN) return;

    int deg  = g_deg[n];
    int dcap = deg < CAP ? deg : CAP;
    int base = n * CAP;

    ull ag0 = 0, ag1 = 0;
    const int go = 4 * lane;

    for (int c0 = 0; c0 < dcap; c0 += 32) {
        int m = dcap - c0; if (m > 32) m = 32;
        int s_l = 0;
        if (lane < m) s_l = g_perm[base + c0 + lane];

        int i = 0;
        for (; i + 8 <= m; i += 8) {
            int sa[8];
            #pragma unroll
            for (int k = 0; k < 8; k++) sa[k] = __shfl_sync(0xffffffffu, s_l, i + k);
            ulonglong2 gv[8];
            #pragma unroll
            for (int k = 0; k < 8; k++) gv[k] = ldg2((const ull*)&g_g[(size_t)sa[k] * D + go]);
            #pragma unroll
            for (int k = 0; k < 8; k++) { add2(ag0, gv[k].x); add2(ag1, gv[k].y); }
        }
        for (; i < m; i++) {
            int s = __shfl_sync(0xffffffffu, s_l, i);
            ulonglong2 gv = ldg2((const ull*)&g_g[(size_t)s * D + go]);
            add2(ag0, gv.x);
            add2(ag1, gv.y);
        }
    }

    float nr = g_norm[n];
    float2 g0 = unpk(ag0), g1 = unpk(ag1);
    red4(&out[(size_t)n * D + 4 * lane],
         make_float4(nr * g0.x, nr * g0.y, nr * g1.x, nr * g1.y));
}

// ---------------- K5: overflow fallback — add missing g contributions ----------------
__global__ void k_ovf(float* __restrict__ out) {
    int cnt = g_novf; if (cnt > 2048) cnt = 2048;
    if (cnt <= 0) return;
    int lane = threadIdx.x & 31;
    int warp = (blockIdx.x * blockDim.x + threadIdx.x) >> 5;
    int nw   = (gridDim.x * blockDim.x) >> 5;
    for (int o = warp; o < cnt; o += nw) {
        int2 v = g_ovf[o];
        int s = v.x, d = v.y;
        float nd = g_norm[d];
        float4 gv = *(const float4*)&g_g[(size_t)s * D + 4 * lane];
        red4(&out[(size_t)d * D + 4 * lane],
             make_float4(nd * gv.x, nd * gv.y, nd * gv.z, nd * gv.w));
    }
}

// ---------------- launch: fork/join two streams inside graph capture ----------------
extern "C" void kernel_launch(void* const* d_in, const int* in_sizes, int n_in,
                              void* d_out, int out_size)
{
    const int*   src   = (const int*)  d_in[0];
    const int*   dst   = (const int*)  d_in[1];
    const float* nfeat = (const float*)d_in[2];
    const float* efeat = (const float*)d_in[3];
    const float* Wn    = (const float*)d_in[4];
    const float* bn    = (const float*)d_in[5];
    const float* We    = (const float*)d_in[6];
    const float* be    = (const float*)d_in[7];
    const float* resid = (const float*)d_in[8];
    float* out = (float*)d_out;

    const int SM_NODE = 128 * 64 * 8 + 128 * 64 * 4;  // 96 KB
    const int SM_G2   = 64 * 64 * 8 + 64 * 64 * 4;    // 48 KB
    cudaFuncSetAttribute(k_gemmN, cudaFuncAttributeMaxDynamicSharedMemorySize, SM_NODE);
    cudaFuncSetAttribute(k_gemm2, cudaFuncAttributeMaxDynamicSharedMemorySize, SM_G2);

    cudaStream_t sA;
    cudaStreamCreateWithFlags(&sA, cudaStreamNonBlocking);
    cudaEvent_t eFork, eNorm, eScale, eEnd;
    cudaEventCreateWithFlags(&eFork,  cudaEventDisableTiming);
    cudaEventCreateWithFlags(&eNorm,  cudaEventDisableTiming);
    cudaEventCreateWithFlags(&eScale, cudaEventDisableTiming);
    cudaEventCreateWithFlags(&eEnd,   cudaEventDisableTiming);

    // fork immediately: the node GEMM depends on nothing
    cudaEventRecord(eFork, 0);
    cudaStreamWaitEvent(sA, eFork, 0);
    k_gemmN<<<782, 256, SM_NODE, sA>>>(nfeat, Wn, bn);

    // s0: prologue chain
    k_zero <<<912, 256>>>();
    k_build<<<(NE + 255) / 256, 256>>>(src, dst);
    k_norm <<<(NN + 255) / 256, 256>>>();
    cudaEventRecord(eNorm, 0);

    // s0: efeat stream (needs norm; in-order on s0)
    k_edge_e<<<3125, 256, 0, 0>>>(src, dst, efeat);

    // sA: scale (needs gemmN [sA order] + norm [event]), then gather chain
    cudaStreamWaitEvent(sA, eNorm, 0);
    k_scale<<<(NN * 32 + 255) / 256, 256, 0, sA>>>(resid, out);
    cudaEventRecord(eScale, sA);
    k_gath<<<6250, 256, 0, sA>>>(out);
    k_ovf <<<16, 256, 0, sA>>>(out);

    // s0: gemm2 (needs edge_e [s0 order] + out base from scale [event])
    cudaStreamWaitEvent(0, eScale, 0);
    k_gemm2<<<782, 256, SM_G2, 0>>>(We, be, out);

    // join side stream back into the capture stream
    cudaEventRecord(eEnd, sA);
    cudaStreamWaitEvent(0, eEnd, 0);
}

// round 13
// speedup vs baseline: 1.0776x; 1.0776x over previous
#include <cuda_runtime.h>
#include <cuda_fp16.h>

#define NN 50000
#define NE 800000
#define D  128
#define DE 64
#define CAP 80

typedef unsigned long long ull;

// ---------------- device scratch (no allocs allowed) ----------------
__device__ __align__(16) int   g_deg [NN];
__device__ __align__(16) float g_norm[NN];
__device__ __align__(16) ull   g_g16 [NN * 32];    // fp16x4 per lane-slot: norm[n]*h[n]
__device__ __align__(16) float g_agge[NN * DE];    // sum_{e->n} norm[src]*efeat
__device__ __align__(16) float g_se  [NN];         // sum_{e->n} norm[src]
__device__ __align__(16) int   g_perm[NN * CAP];   // per-dst src list
__device__ __align__(16) int2  g_ovf [2048];       // overflow {src, dst}
__device__ int g_novf;

// ---------------- PTX helpers ----------------
__device__ __forceinline__ void fma2(ull &d, ull a, ull b) {
    asm("fma.rn.f32x2 %0, %1, %2, %0;" : "+l"(d) : "l"(a), "l"(b));
}
__device__ __forceinline__ ull dup2(float x) {
    ull r; asm("mov.b64 %0, {%1, %1};" : "=l"(r) : "f"(x)); return r;
}
__device__ __forceinline__ ull pack2(float a, float b) {
    ull r; asm("mov.b64 %0, {%1, %2};" : "=l"(r) : "f"(a), "f"(b)); return r;
}
__device__ __forceinline__ float2 unpk(ull v) {
    float2 r; asm("mov.b64 {%0, %1}, %2;" : "=f"(r.x), "=f"(r.y) : "l"(v)); return r;
}
__device__ __forceinline__ void red4(float* p, float4 v) {
    asm volatile("red.global.add.v4.f32 [%0], {%1, %2, %3, %4};"
                 :: "l"(p), "f"(v.x), "f"(v.y), "f"(v.z), "f"(v.w) : "memory");
}
__device__ __forceinline__ ull ldg1(const ull* p) {
    ull r; asm("ld.global.nc.u64 %0, [%1];" : "=l"(r) : "l"(p)); return r;
}
// streaming 16B load with evict-first policy
__device__ __forceinline__ float4 ldg4_ef(const float* p, ull pol) {
    float4 r;
    asm("ld.global.nc.L2::cache_hint.v4.f32 {%0, %1, %2, %3}, [%4], %5;"
        : "=f"(r.x), "=f"(r.y), "=f"(r.z), "=f"(r.w) : "l"(p), "l"(pol));
    return r;
}
__device__ __forceinline__ float ldgf(const float* p) {
    float r; asm("ld.global.nc.f32 %0, [%1];" : "=f"(r) : "l"(p)); return r;
}
// pack 4 floats to fp16x4 in one u64
__device__ __forceinline__ ull pack_h4(float a, float b, float c, float d) {
    __half2 h01 = __floats2half2_rn(a, b);
    __half2 h23 = __floats2half2_rn(c, d);
    unsigned u0 = *(unsigned*)&h01, u1 = *(unsigned*)&h23;
    return ((ull)u1 << 32) | u0;
}
// unpack fp16x4 and accumulate into float4
__device__ __forceinline__ void acc_h4(float4 &acc, ull v) {
    unsigned lo = (unsigned)v, hi = (unsigned)(v >> 32);
    float2 f01 = __half22float2(*(__half2*)&lo);
    float2 f23 = __half22float2(*(__half2*)&hi);
    acc.x += f01.x; acc.y += f01.y; acc.z += f23.x; acc.w += f23.y;
}

// ---------------- K0: zero scratch ----------------
__global__ void k_zero() {
    int i = blockIdx.x * blockDim.x + threadIdx.x;
    int st = gridDim.x * blockDim.x;
    float4 z = make_float4(0.f, 0.f, 0.f, 0.f);
    for (int j = i; j < NN * DE / 4; j += st) ((float4*)g_agge)[j] = z;
    for (int j = i; j < NN; j += st) { g_se[j] = 0.f; g_deg[j] = 0; }
    if (i == 0) g_novf = 0;
}

// ---------------- K1: build per-dst src buckets + degree ----------------
__global__ void k_build(const int* __restrict__ src, const int* __restrict__ dst) {
    int e = blockIdx.x * blockDim.x + threadIdx.x;
    if (e >= NE) return;
    int d = dst[e], s = src[e];
    int c = atomicAdd(&g_deg[d], 1);
    if (c < CAP) {
        g_perm[d * CAP + c] = s;
    } else {
        int o = atomicAdd(&g_novf, 1);
        if (o < 2048) g_ovf[o] = make_int2(s, d);
    }
}

// ---------------- K1b: norm = (deg+1)^-1/2 ----------------
__global__ void k_norm() {
    int i = blockIdx.x * blockDim.x + threadIdx.x;
    if (i < NN) g_norm[i] = rsqrtf((float)g_deg[i] + 1.0f);
}

// ---------------- KA: edge-parallel efeat scatter (2 edges per round) ----------------
__global__ __launch_bounds__(256) void k_edge_e(
    const int* __restrict__ src, const int* __restrict__ dst,
    const float* __restrict__ efeat)
{
    int lane = threadIdx.x & 31;
    int warp = (blockIdx.x * blockDim.x + threadIdx.x) >> 5;   // 25000 warps
    int e0   = warp * 32;
    if (e0 >= NE) return;

    int s = src[e0 + lane];
    int d = dst[e0 + lane];
    float ns = ldgf(&g_norm[s]);
    atomicAdd(&g_se[d], ns);

    ull pol;
    asm("createpolicy.fractional.L2::evict_first.b64 %0, 1.0;" : "=l"(pol));

    int half = lane >> 4;        // 0 or 1: which edge of the pair
    int l16  = lane & 15;
    const float* ep = &efeat[(size_t)e0 * DE + 4 * l16];

    #pragma unroll
    for (int j = 0; j < 32; j += 2) {
        int idx = j + half;
        int   dj  = __shfl_sync(0xffffffffu, d, idx);
        float nsj = __shfl_sync(0xffffffffu, ns, idx);
        float4 ev = ldg4_ef(ep + (size_t)idx * DE, pol);
        red4(&g_agge[(size_t)dj * DE + 4 * l16],
             make_float4(nsj * ev.x, nsj * ev.y, nsj * ev.z, nsj * ev.w));
    }
}

// ---------------- K2: node GEMM  g16 = fp16(norm*(nfeat@Wn+bn));  out = (h+resid)/deg ---
__global__ __launch_bounds__(256) void k_node(
    const float* __restrict__ nfeat, const float* __restrict__ Wn,
    const float* __restrict__ bn, const float* __restrict__ resid,
    float* __restrict__ out)
{
    extern __shared__ ull smn[];
    ull*   sW  = smn;                       // [128][64] u64 (Wn dim-pairs) = 64 KB
    float* sNf = (float*)(smn + 128 * 64);  // [k][node] = 32 KB

    int t = threadIdx.x, lane = t & 31, w = t >> 5;

    const ulonglong2* Wn128 = (const ulonglong2*)Wn;
    ulonglong2* sW2 = (ulonglong2*)sW;
    for (int i = t; i < 128 * 64 / 2; i += 256) sW2[i] = Wn128[i];

    float4 bnv = *(const float4*)&bn[4 * lane];
    ull b01 = pack2(bnv.x, bnv.y), b23 = pack2(bnv.z, bnv.w);
    float4 r4 = *(const float4*)&resid[4 * lane];

    int nodeL = t & 63;   // load-phase node
    int q     = t >> 6;   // load-phase dim quarter

    const int NT = (NN + 63) / 64;
    for (int tile = blockIdx.x; tile < NT; tile += gridDim.x) {
        __syncthreads();
        int gn = tile * 64 + nodeL;
        #pragma unroll
        for (int i = 0; i < 8; i++) {
            int k0 = 32 * q + 4 * i;
            float4 v = make_float4(0.f, 0.f, 0.f, 0.f);
            if (gn < NN) v = *(const float4*)&nfeat[(size_t)gn * D + k0];
            sNf[(k0 + 0) * 64 + nodeL] = v.x;
            sNf[(k0 + 1) * 64 + nodeL] = v.y;
            sNf[(k0 + 2) * 64 + nodeL] = v.z;
            sNf[(k0 + 3) * 64 + nodeL] = v.w;
        }
        __syncthreads();

        ull acc[8][2];
        #pragma unroll
        for (int j = 0; j < 8; j++) { acc[j][0] = b01; acc[j][1] = b23; }

        #pragma unroll 8
        for (int k = 0; k < 128; k++) {
            ulonglong2 wv = *(const ulonglong2*)&sW[k * 64 + 2 * lane];
            float4 f0 = *(const float4*)&sNf[k * 64 + 8 * w];
            float4 f1 = *(const float4*)&sNf[k * 64 + 8 * w + 4];
            float fv[8] = {f0.x, f0.y, f0.z, f0.w, f1.x, f1.y, f1.z, f1.w};
            #pragma unroll
            for (int j = 0; j < 8; j++) {
                ull dj = dup2(fv[j]);
                fma2(acc[j][0], dj, wv.x);
                fma2(acc[j][1], dj, wv.y);
            }
        }

        #pragma unroll
        for (int j = 0; j < 8; j++) {
            int n = tile * 64 + 8 * w + j;
            if (n >= NN) continue;
            float dv  = (float)g_deg[n] + 1.0f;
            float inv = 1.0f / dv;
            float nr  = rsqrtf(dv);
            float2 p0 = unpk(acc[j][0]), p1 = unpk(acc[j][1]);
            g_g16[(size_t)n * 32 + lane] =
                pack_h4(nr * p0.x, nr * p0.y, nr * p1.x, nr * p1.y);
            *(float4*)&out[(size_t)n * D + 4 * lane] =
                make_float4((p0.x + r4.x) * inv, (p0.y + r4.y) * inv,
                            (p1.x + r4.z) * inv, (p1.y + r4.w) * inv);
        }
    }
}

// ---------------- K3: tiled GEMM  out += norm * (agge@We + se*be)  [red4] ----------
__global__ __launch_bounds__(256) void k_gemm2(
    const float* __restrict__ We, const float* __restrict__ be,
    float* __restrict__ out)
{
    extern __shared__ ull smg[];
    ull*   sWe = smg;                      // [64][64] u64 (We dim-pairs) = 32 KB
    float* sAg = (float*)(smg + 64 * 64);  // [k][node] = 16 KB

    int t = threadIdx.x, lane = t & 31, w = t >> 5;

    const ulonglong2* We128 = (const ulonglong2*)We;
    ulonglong2* sWe2 = (ulonglong2*)sWe;
    for (int i = t; i < 64 * 64 / 2; i += 256) sWe2[i] = We128[i];

    float4 be4 = *(const float4*)&be[4 * lane];

    int nodeL = t & 63;
    int q     = t >> 6;   // 4 quarters x 16 k each

    const int NT = (NN + 63) / 64;
    for (int tile = blockIdx.x; tile < NT; tile += gridDim.x) {
        __syncthreads();
        int gn = tile * 64 + nodeL;
        #pragma unroll
        for (int i = 0; i < 4; i++) {
            int k0 = 16 * q + 4 * i;
            float4 v = make_float4(0.f, 0.f, 0.f, 0.f);
            if (gn < NN) v = *(const float4*)&g_agge[(size_t)gn * DE + k0];
            sAg[(k0 + 0) * 64 + nodeL] = v.x;
            sAg[(k0 + 1) * 64 + nodeL] = v.y;
            sAg[(k0 + 2) * 64 + nodeL] = v.z;
            sAg[(k0 + 3) * 64 + nodeL] = v.w;
        }
        __syncthreads();

        ull acc[8][2];
        #pragma unroll
        for (int j = 0; j < 8; j++) { acc[j][0] = 0ULL; acc[j][1] = 0ULL; }

        #pragma unroll 8
        for (int k = 0; k < 64; k++) {
            ulonglong2 wv = *(const ulonglong2*)&sWe[k * 64 + 2 * lane];
            float4 f0 = *(const float4*)&sAg[k * 64 + 8 * w];
            float4 f1 = *(const float4*)&sAg[k * 64 + 8 * w + 4];
            float fv[8] = {f0.x, f0.y, f0.z, f0.w, f1.x, f1.y, f1.z, f1.w};
            #pragma unroll
            for (int j = 0; j < 8; j++) {
                ull dj = dup2(fv[j]);
                fma2(acc[j][0], dj, wv.x);
                fma2(acc[j][1], dj, wv.y);
            }
        }

        #pragma unroll
        for (int j = 0; j < 8; j++) {
            int n = tile * 64 + 8 * w + j;
            if (n >= NN) continue;
            float nr = g_norm[n];
            float se = g_se[n];
            float2 p0 = unpk(acc[j][0]), p1 = unpk(acc[j][1]);
            red4(&out[(size_t)n * D + 4 * lane],
                 make_float4(nr * (p0.x + se * be4.x), nr * (p0.y + se * be4.y),
                             nr * (p1.x + se * be4.z), nr * (p1.y + se * be4.w)));
        }
    }
}

// ---------------- K4: node-parallel fp16 g gather (no smem; red4 epilogue) -------------
__global__ __launch_bounds__(256) void k_gath(float* __restrict__ out)
{
    int t = threadIdx.x, lane = t & 31, w = t >> 5;
    int n = blockIdx.x * 8 + w;   // grid = 6250 * 8 warps = 50000
    if (n >= NN) return;

    int deg  = g_deg[n];
    int dcap = deg < CAP ? deg : CAP;
    int base = n * CAP;

    float4 acc = make_float4(0.f, 0.f, 0.f, 0.f);

    for (int c0 = 0; c0 < dcap; c0 += 32) {
        int m = dcap - c0; if (m > 32) m = 32;
        int s_l = 0;
        if (lane < m) s_l = g_perm[base + c0 + lane];

        int i = 0;
        for (; i + 8 <= m; i += 8) {
            int sa[8];
            #pragma unroll
            for (int k = 0; k < 8; k++) sa[k] = __shfl_sync(0xffffffffu, s_l, i + k);
            ull gv[8];
            #pragma unroll
            for (int k = 0; k < 8; k++) gv[k] = ldg1(&g_g16[(size_t)sa[k] * 32 + lane]);
            #pragma unroll
            for (int k = 0; k < 8; k++) acc_h4(acc, gv[k]);
        }
        for (; i < m; i++) {
            int s = __shfl_sync(0xffffffffu, s_l, i);
            ull gv = ldg1(&g_g16[(size_t)s * 32 + lane]);
            acc_h4(acc, gv);
        }
    }

    float nr = g_norm[n];
    red4(&out[(size_t)n * D + 4 * lane],
         make_float4(nr * acc.x, nr * acc.y, nr * acc.z, nr * acc.w));
}

// ---------------- K5: overflow fallback — add missing g contributions ----------------
__global__ void k_ovf(float* __restrict__ out) {
    int cnt = g_novf; if (cnt > 2048) cnt = 2048;
    if (cnt <= 0) return;
    int lane = threadIdx.x & 31;
    int warp = (blockIdx.x * blockDim.x + threadIdx.x) >> 5;
    int nw   = (gridDim.x * blockDim.x) >> 5;
    for (int o = warp; o < cnt; o += nw) {
        int2 v = g_ovf[o];
        int s = v.x, d = v.y;
        float nd = g_norm[d];
        float4 acc = make_float4(0.f, 0.f, 0.f, 0.f);
        acc_h4(acc, g_g16[(size_t)s * 32 + lane]);
        red4(&out[(size_t)d * D + 4 * lane],
             make_float4(nd * acc.x, nd * acc.y, nd * acc.z, nd * acc.w));
    }
}

// ---------------- launch: fork/join two streams inside graph capture ----------------
extern "C" void kernel_launch(void* const* d_in, const int* in_sizes, int n_in,
                              void* d_out, int out_size)
{
    const int*   src   = (const int*)  d_in[0];
    const int*   dst   = (const int*)  d_in[1];
    const float* nfeat = (const float*)d_in[2];
    const float* efeat = (const float*)d_in[3];
    const float* Wn    = (const float*)d_in[4];
    const float* bn    = (const float*)d_in[5];
    const float* We    = (const float*)d_in[6];
    const float* be    = (const float*)d_in[7];
    const float* resid = (const float*)d_in[8];
    float* out = (float*)d_out;

    const int SM_NODE = 128 * 64 * 8 + 128 * 64 * 4;  // 96 KB
    const int SM_G2   = 64 * 64 * 8 + 64 * 64 * 4;    // 48 KB
    cudaFuncSetAttribute(k_node,  cudaFuncAttributeMaxDynamicSharedMemorySize, SM_NODE);
    cudaFuncSetAttribute(k_gemm2, cudaFuncAttributeMaxDynamicSharedMemorySize, SM_G2);

    cudaStream_t sA;
    cudaStreamCreateWithFlags(&sA, cudaStreamNonBlocking);
    cudaEvent_t eFork, eNode, eEnd;
    cudaEventCreateWithFlags(&eFork, cudaEventDisableTiming);
    cudaEventCreateWithFlags(&eNode, cudaEventDisableTiming);
    cudaEventCreateWithFlags(&eEnd,  cudaEventDisableTiming);

    // serial prologue on the capture stream
    k_zero <<<912, 256>>>();
    k_build<<<(NE + 255) / 256, 256>>>(src, dst);
    k_norm <<<(NN + 255) / 256, 256>>>();

    // fork: side stream joins the capture
    cudaEventRecord(eFork, 0);
    cudaStreamWaitEvent(sA, eFork, 0);

    // sA: compute-bound chain        // s0: memory-bound chain (concurrent)
    k_node  <<<782, 256, SM_NODE, sA>>>(nfeat, Wn, bn, resid, out);
    k_edge_e<<<3125, 256, 0, 0>>>(src, dst, efeat);

    cudaEventRecord(eNode, sA);
    k_gath<<<6250, 256, 0, sA>>>(out);           // needs g_g16 + out base (sA order)
    k_ovf <<<16, 256, 0, sA>>>(out);

    cudaStreamWaitEvent(0, eNode, 0);            // gemm2 needs out base from k_node
    k_gemm2<<<782, 256, SM_G2, 0>>>(We, be, out); // after edge_e (s0 order) + eNode

    // join side stream back into the capture stream
    cudaEventRecord(eEnd, sA);
    cudaStreamWaitEvent(0, eEnd, 0);
}